// round 1
// baseline (speedup 1.0000x reference)
#include <cuda_runtime.h>
#include <math.h>

// Problem constants
#define BB      4
#define SS      2048
#define DMODEL  1024
#define NH      16
#define HDIM    64
#define MR      (BB*SS)        // 8192 rows

// ---------------------------------------------------------------------------
// Scratch (device globals — no allocation allowed in kernel_launch)
// ---------------------------------------------------------------------------
__device__ float g_Qp[MR*DMODEL];   // projected Q  [b*S+s][h*64+d]
__device__ float g_Kp[MR*DMODEL];   // projected K
__device__ float g_Vp[MR*DMODEL];   // projected V
__device__ float g_Ao[MR*DMODEL];   // attention output (pre-Wo)
__device__ float g_cm[BB*NH*SS];    // per-column max   m[k]
__device__ float g_cr[BB*NH*SS];    // per-column scale 1/(8*Z[k])

// ---------------------------------------------------------------------------
// Kernel 1: C[M,N] = A[M,K] @ W[K,N] + bias[N]
// 128x128 tile, BK=8, 256 threads, 8x8 per-thread microtile.
// ---------------------------------------------------------------------------
__global__ __launch_bounds__(256) void sgemm_bias(
    const float* __restrict__ A, const float* __restrict__ W,
    const float* __restrict__ bias, float* __restrict__ C,
    int M, int N, int K)
{
    __shared__ float As[8][128];   // transposed A tile: [k][m]
    __shared__ float Bs[8][128];   // W tile:            [k][n]

    const int tid  = threadIdx.x;
    const int ty   = tid >> 4;          // 0..15
    const int tx   = tid & 15;          // 0..15
    const int brow = blockIdx.y << 7;
    const int bcol = blockIdx.x << 7;

    const int arow = tid >> 1;          // 0..127
    const int acol = (tid & 1) << 2;    // 0 or 4
    const int wrow = tid >> 5;          // 0..7
    const int wcol = (tid & 31) << 2;   // 0..124

    const float* Ap = A + (size_t)(brow + arow) * K + acol;
    const float* Wp = W + (size_t)wrow * N + bcol + wcol;

    float acc[8][8];
#pragma unroll
    for (int i = 0; i < 8; i++)
#pragma unroll
        for (int j = 0; j < 8; j++) acc[i][j] = 0.f;

    for (int k0 = 0; k0 < K; k0 += 8) {
        float4 av = *(const float4*)(Ap + k0);
        float4 wv = *(const float4*)(Wp + (size_t)k0 * N);
        As[acol+0][arow] = av.x;
        As[acol+1][arow] = av.y;
        As[acol+2][arow] = av.z;
        As[acol+3][arow] = av.w;
        *(float4*)&Bs[wrow][wcol] = wv;
        __syncthreads();

#pragma unroll
        for (int kk = 0; kk < 8; kk++) {
            float4 a0 = *(const float4*)&As[kk][(ty<<3)];
            float4 a1 = *(const float4*)&As[kk][(ty<<3)+4];
            float4 b0 = *(const float4*)&Bs[kk][(tx<<3)];
            float4 b1 = *(const float4*)&Bs[kk][(tx<<3)+4];
            float ar[8] = {a0.x,a0.y,a0.z,a0.w,a1.x,a1.y,a1.z,a1.w};
            float br[8] = {b0.x,b0.y,b0.z,b0.w,b1.x,b1.y,b1.z,b1.w};
#pragma unroll
            for (int i = 0; i < 8; i++)
#pragma unroll
                for (int j = 0; j < 8; j++)
                    acc[i][j] += ar[i] * br[j];
        }
        __syncthreads();
    }

#pragma unroll
    for (int i = 0; i < 8; i++) {
        const int row = brow + (ty<<3) + i;
        float* Cp = C + (size_t)row * N + bcol + (tx<<3);
        float4 bv0 = *(const float4*)(bias + bcol + (tx<<3));
        float4 bv1 = *(const float4*)(bias + bcol + (tx<<3) + 4);
        float4 o0, o1;
        o0.x = acc[i][0]+bv0.x; o0.y = acc[i][1]+bv0.y;
        o0.z = acc[i][2]+bv0.z; o0.w = acc[i][3]+bv0.w;
        o1.x = acc[i][4]+bv1.x; o1.y = acc[i][5]+bv1.y;
        o1.z = acc[i][6]+bv1.z; o1.w = acc[i][7]+bv1.w;
        *(float4*)Cp       = o0;
        *(float4*)(Cp + 4) = o1;
    }
}

// ---------------------------------------------------------------------------
// Kernel 2: column softmax stats. For each (b,h,k): m[k]=max_q s, Z=sum exp.
// One thread per key column; Q tiles staged through smem (broadcast reads).
// grid = (B*H, S/256), block = 256
// ---------------------------------------------------------------------------
__global__ __launch_bounds__(256) void col_stats(
    const float* __restrict__ Qp, const float* __restrict__ Kp,
    float* __restrict__ cm, float* __restrict__ cr)
{
    __shared__ float Qs[128*64];
    const int tid = threadIdx.x;
    const int bh  = blockIdx.x;
    const int b   = bh >> 4, h = bh & 15;
    const int k   = (blockIdx.y << 8) + tid;
    const size_t base = (size_t)b * SS * DMODEL + (size_t)h * HDIM;

    // own key column -> registers
    float kr[64];
    {
        const float4* kp4 = (const float4*)(Kp + base + (size_t)k * DMODEL);
#pragma unroll
        for (int i = 0; i < 16; i++) {
            float4 v = kp4[i];
            kr[4*i+0] = v.x; kr[4*i+1] = v.y; kr[4*i+2] = v.z; kr[4*i+3] = v.w;
        }
    }

    float m = -1e30f, z = 0.f;
    for (int q0 = 0; q0 < SS; q0 += 128) {
        __syncthreads();
#pragma unroll
        for (int it = 0; it < 8; it++) {
            int idx4 = it*256 + tid;
            int qq = idx4 >> 4, c4 = (idx4 & 15) << 2;
            float4 v = *(const float4*)(Qp + base + (size_t)(q0+qq)*DMODEL + c4);
            *(float4*)&Qs[qq*64 + c4] = v;
        }
        __syncthreads();

        for (int q = 0; q < 128; q++) {
            const float4* q4 = (const float4*)&Qs[q*64];
            float sa0 = 0.f, sa1 = 0.f, sa2 = 0.f, sa3 = 0.f;
#pragma unroll
            for (int d4 = 0; d4 < 16; d4 += 4) {
                float4 v0 = q4[d4+0], v1 = q4[d4+1], v2 = q4[d4+2], v3 = q4[d4+3];
                sa0 += v0.x*kr[4*d4+ 0] + v0.y*kr[4*d4+ 1] + v0.z*kr[4*d4+ 2] + v0.w*kr[4*d4+ 3];
                sa1 += v1.x*kr[4*d4+ 4] + v1.y*kr[4*d4+ 5] + v1.z*kr[4*d4+ 6] + v1.w*kr[4*d4+ 7];
                sa2 += v2.x*kr[4*d4+ 8] + v2.y*kr[4*d4+ 9] + v2.z*kr[4*d4+10] + v2.w*kr[4*d4+11];
                sa3 += v3.x*kr[4*d4+12] + v3.y*kr[4*d4+13] + v3.z*kr[4*d4+14] + v3.w*kr[4*d4+15];
            }
            float s = (sa0 + sa1) + (sa2 + sa3);
            float mn = fmaxf(m, s);
            z = z * __expf(m - mn) + __expf(s - mn);
            m = mn;
        }
    }
    cm[(size_t)bh*SS + k] = m;
    cr[(size_t)bh*SS + k] = 1.0f / (z * 8.0f);   // fold 1/sqrt(HD)=1/8
}

// ---------------------------------------------------------------------------
// Kernel 3: fused score recompute + column-softmax apply + E@V.
// Block: 128 q rows x full head. k tiled by 64. 256 threads.
// ---------------------------------------------------------------------------
#define QS_STRIDE 132
#define ES_STRIDE 132
#define KS_STRIDE 68
#define ATT_SMEM  ((64*QS_STRIDE + 64*ES_STRIDE + 64*KS_STRIDE + 64*64 + 128) * 4)

__global__ __launch_bounds__(256) void attn_av(
    const float* __restrict__ Qp, const float* __restrict__ Kp,
    const float* __restrict__ Vp, const float* __restrict__ cm,
    const float* __restrict__ cr, float* __restrict__ Ao)
{
    extern __shared__ float sm[];
    float* QsT = sm;                         // [d][q]  64 x QS_STRIDE
    float* EsT = QsT + 64*QS_STRIDE;         // [k][q]  64 x ES_STRIDE
    float* KsT = EsT + 64*ES_STRIDE;         // [d][k]  64 x KS_STRIDE
    float* Vs  = KsT + 64*KS_STRIDE;         // [k][d]  64 x 64
    float* mS  = Vs + 64*64;                 // [64]
    float* rS  = mS + 64;                    // [64]

    const int tid = threadIdx.x;
    const int ty  = tid >> 4;                // 0..15 -> 8 q rows
    const int tx  = tid & 15;                // 0..15 -> 4 cols (k or d)
    const int bh  = blockIdx.x;
    const int b   = bh >> 4, h = bh & 15;
    const int q0  = blockIdx.y << 7;
    const size_t base = (size_t)b * SS * DMODEL + (size_t)h * HDIM;

    // Load 128x64 Q tile, transposed to [d][q]
#pragma unroll
    for (int it = 0; it < 8; it++) {
        int idx4 = it*256 + tid;
        int qq = idx4 >> 4, d4 = (idx4 & 15) << 2;
        float4 v = *(const float4*)(Qp + base + (size_t)(q0+qq)*DMODEL + d4);
        QsT[(d4+0)*QS_STRIDE + qq] = v.x;
        QsT[(d4+1)*QS_STRIDE + qq] = v.y;
        QsT[(d4+2)*QS_STRIDE + qq] = v.z;
        QsT[(d4+3)*QS_STRIDE + qq] = v.w;
    }

    float oacc[8][4];
#pragma unroll
    for (int i = 0; i < 8; i++)
#pragma unroll
        for (int j = 0; j < 4; j++) oacc[i][j] = 0.f;

    for (int kt = 0; kt < SS; kt += 64) {
        __syncthreads();   // previous stage B done with EsT/KsT/Vs
        // Load K (transposed) and V tiles
#pragma unroll
        for (int it = 0; it < 4; it++) {
            int idx4 = it*256 + tid;
            int kk = idx4 >> 4, d4 = (idx4 & 15) << 2;
            float4 kv = *(const float4*)(Kp + base + (size_t)(kt+kk)*DMODEL + d4);
            KsT[(d4+0)*KS_STRIDE + kk] = kv.x;
            KsT[(d4+1)*KS_STRIDE + kk] = kv.y;
            KsT[(d4+2)*KS_STRIDE + kk] = kv.z;
            KsT[(d4+3)*KS_STRIDE + kk] = kv.w;
            float4 vv = *(const float4*)(Vp + base + (size_t)(kt+kk)*DMODEL + d4);
            *(float4*)&Vs[kk*64 + d4] = vv;
        }
        if (tid < 64) {
            mS[tid] = cm[(size_t)bh*SS + kt + tid];
            rS[tid] = cr[(size_t)bh*SS + kt + tid];
        }
        __syncthreads();

        // Stage A: s tile [128q x 64k], thread = 8q x 4k
        float sacc[8][4];
#pragma unroll
        for (int i = 0; i < 8; i++)
#pragma unroll
            for (int j = 0; j < 4; j++) sacc[i][j] = 0.f;

        for (int d = 0; d < 64; d++) {
            float4 a0 = *(const float4*)&QsT[d*QS_STRIDE + (ty<<3)];
            float4 a1 = *(const float4*)&QsT[d*QS_STRIDE + (ty<<3) + 4];
            float4 kv = *(const float4*)&KsT[d*KS_STRIDE + (tx<<2)];
            float ar[8] = {a0.x,a0.y,a0.z,a0.w,a1.x,a1.y,a1.z,a1.w};
            float kw[4] = {kv.x,kv.y,kv.z,kv.w};
#pragma unroll
            for (int i = 0; i < 8; i++)
#pragma unroll
                for (int j = 0; j < 4; j++)
                    sacc[i][j] += ar[i] * kw[j];
        }
        float mg[4], rg[4];
#pragma unroll
        for (int j = 0; j < 4; j++) {
            mg[j] = mS[(tx<<2)+j];
            rg[j] = rS[(tx<<2)+j];
        }
#pragma unroll
        for (int j = 0; j < 4; j++)
#pragma unroll
            for (int i = 0; i < 8; i++)
                EsT[((tx<<2)+j)*ES_STRIDE + (ty<<3) + i] =
                    __expf(sacc[i][j] - mg[j]) * rg[j];
        __syncthreads();

        // Stage B: out[q,d] += E[q,k] * V[k,d]; thread = 8q x 4d
        for (int kk = 0; kk < 64; kk++) {
            float4 e0 = *(const float4*)&EsT[kk*ES_STRIDE + (ty<<3)];
            float4 e1 = *(const float4*)&EsT[kk*ES_STRIDE + (ty<<3) + 4];
            float4 vv = *(const float4*)&Vs[kk*64 + (tx<<2)];
            float er[8] = {e0.x,e0.y,e0.z,e0.w,e1.x,e1.y,e1.z,e1.w};
            float vw[4] = {vv.x,vv.y,vv.z,vv.w};
#pragma unroll
            for (int i = 0; i < 8; i++)
#pragma unroll
                for (int j = 0; j < 4; j++)
                    oacc[i][j] += er[i] * vw[j];
        }
    }

    // Write merged-head layout [b, q, h*64 + d]
#pragma unroll
    for (int i = 0; i < 8; i++) {
        float4 o = {oacc[i][0], oacc[i][1], oacc[i][2], oacc[i][3]};
        *(float4*)(Ao + base + (size_t)(q0 + (ty<<3) + i)*DMODEL + (tx<<2)) = o;
    }
}

// ---------------------------------------------------------------------------
// Launch
// ---------------------------------------------------------------------------
extern "C" void kernel_launch(void* const* d_in, const int* in_sizes, int n_in,
                              void* d_out, int out_size)
{
    const float* qin = (const float*)d_in[0];
    const float* kin = (const float*)d_in[1];
    const float* vin = (const float*)d_in[2];
    const float* Wq  = (const float*)d_in[3];
    const float* bq  = (const float*)d_in[4];
    const float* Wk  = (const float*)d_in[5];
    const float* bk  = (const float*)d_in[6];
    const float* Wv  = (const float*)d_in[7];
    const float* bv  = (const float*)d_in[8];
    const float* Wo  = (const float*)d_in[9];
    const float* bo  = (const float*)d_in[10];

    float *Qp, *Kp, *Vp, *Ao, *cm, *cr;
    cudaGetSymbolAddress((void**)&Qp, g_Qp);
    cudaGetSymbolAddress((void**)&Kp, g_Kp);
    cudaGetSymbolAddress((void**)&Vp, g_Vp);
    cudaGetSymbolAddress((void**)&Ao, g_Ao);
    cudaGetSymbolAddress((void**)&cm, g_cm);
    cudaGetSymbolAddress((void**)&cr, g_cr);

    cudaFuncSetAttribute(attn_av, cudaFuncAttributeMaxDynamicSharedMemorySize,
                         ATT_SMEM);

    dim3 gGemm(DMODEL/128, MR/128);   // (8, 64)

    sgemm_bias<<<gGemm, 256>>>(qin, Wq, bq, Qp, MR, DMODEL, DMODEL);
    sgemm_bias<<<gGemm, 256>>>(kin, Wk, bk, Kp, MR, DMODEL, DMODEL);
    sgemm_bias<<<gGemm, 256>>>(vin, Wv, bv, Vp, MR, DMODEL, DMODEL);

    col_stats<<<dim3(BB*NH, SS/256), 256>>>(Qp, Kp, cm, cr);

    attn_av<<<dim3(BB*NH, SS/128), 256, ATT_SMEM>>>(Qp, Kp, Vp, cm, cr, Ao);

    sgemm_bias<<<gGemm, 256>>>(Ao, Wo, bo, (float*)d_out, MR, DMODEL, DMODEL);
}